// round 2
// baseline (speedup 1.0000x reference)
#include <cuda_runtime.h>
#include <math.h>

#define LAYERS 4
#define HIDDEN 512
#define FFND   1024
#define HEADS  4
#define BB     2
#define SSEQ   2048
#define HD     128
#define NROWS  (BB*SSEQ)   // 4096
#define EPS    1e-5f

// ---------------- device scratch (no runtime allocation allowed) ----------------
__device__ float g_X [NROWS*HIDDEN];
__device__ float g_Xn[NROWS*HIDDEN];
__device__ float g_Q [NROWS*HIDDEN];
__device__ float g_K [NROWS*HIDDEN];
__device__ float g_V [NROWS*HIDDEN];
__device__ float g_Yh[NROWS*HIDDEN];
__device__ float g_G [NROWS*HIDDEN];
__device__ float g_P [NROWS*HIDDEN];
__device__ float g_Y [NROWS*HIDDEN];
__device__ float g_Yn[NROWS*HIDDEN];
__device__ float g_F [NROWS*FFND];
__device__ float g_pow[HEADS*SSEQ];
__device__ float g_cu[SSEQ*HD];
__device__ float g_su[SSEQ*HD];
__device__ float g_cd[SSEQ*HD];
__device__ float g_sd[SSEQ*HD];

// ---------------- precompute tables ----------------
__global__ void xpos_tables_kernel(float* cu, float* su, float* cd, float* sd)
{
    int idx = blockIdx.x * blockDim.x + threadIdx.x;
    if (idx >= SSEQ * HD) return;
    int pos = idx / HD;
    int e   = idx % HD;
    int j   = e >> 1;
    float sj = (2.0f * (float)j + 0.4f * (float)HD) / (1.4f * (float)HD);
    double scale = pow((double)sj, (double)pos / 512.0);
    float invf = (float)(1.0 / pow(10000.0, (double)j / 64.0));
    float angf = (float)pos * invf;          // reference rounds ang to f32
    double ang = (double)angf;
    float sn = (float)sin(ang);
    float cs = (float)cos(ang);
    float sc  = (float)scale;
    float isc = (float)(1.0 / scale);
    cu[idx] = cs * sc;  su[idx] = sn * sc;    // Q (upscale)
    cd[idx] = cs * isc; sd[idx] = sn * isc;   // K (downscale)
}

__global__ void pow_kernel(float* powtab)
{
    int idx = blockIdx.x * blockDim.x + threadIdx.x;
    if (idx >= HEADS * SSEQ) return;
    int h = idx / SSEQ;
    int d = idx % SSEQ;
    double lg = log(1.0/32.0) + (double)h * (log(1.0/512.0) - log(1.0/32.0)) / (double)(HEADS - 1);
    double gamma = 1.0 - exp(lg);
    powtab[idx] = (float)exp((double)d * log(gamma));
}

// ---------------- xPos apply (in place, pair-owning threads) ----------------
__global__ void xpos_apply_kernel(float* __restrict__ X,
                                  const float* __restrict__ ct,
                                  const float* __restrict__ st)
{
    int idx = blockIdx.x * blockDim.x + threadIdx.x;   // NROWS*256 pairs
    if (idx >= NROWS * 256) return;
    int r  = idx >> 8;
    int pe = idx & 255;
    int h  = pe >> 6;
    int j  = pe & 63;
    int pos = r & (SSEQ - 1);
    size_t base = (size_t)r * HIDDEN + h * HD + 2 * j;
    float x1 = X[base], x2 = X[base + 1];
    int ti = pos * HD + 2 * j;
    float c = ct[ti], s = st[ti];
    X[base]     = x1 * c - x2 * s;
    X[base + 1] = x2 * c + x1 * s;
}

// ---------------- LayerNorm: one block per row (512) ----------------
__global__ void __launch_bounds__(128) ln_kernel(const float* __restrict__ X,
                                                 const float* __restrict__ w,
                                                 const float* __restrict__ b,
                                                 float* __restrict__ out)
{
    int row = blockIdx.x;
    int tid = threadIdx.x;
    float4 x = *(const float4*)&X[(size_t)row * HIDDEN + tid * 4];
    float s = x.x + x.y + x.z + x.w;
    float q = x.x*x.x + x.y*x.y + x.z*x.z + x.w*x.w;
    #pragma unroll
    for (int o = 16; o > 0; o >>= 1) {
        s += __shfl_xor_sync(0xffffffffu, s, o);
        q += __shfl_xor_sync(0xffffffffu, q, o);
    }
    __shared__ float ss[4], qq[4];
    if ((tid & 31) == 0) { ss[tid >> 5] = s; qq[tid >> 5] = q; }
    __syncthreads();
    float S  = ss[0] + ss[1] + ss[2] + ss[3];
    float Qs = qq[0] + qq[1] + qq[2] + qq[3];
    float mean = S * (1.0f / HIDDEN);
    float var  = Qs * (1.0f / HIDDEN) - mean * mean;
    float inv  = rsqrtf(var + EPS);
    float4 wv = *(const float4*)&w[tid * 4];
    float4 bv = *(const float4*)&b[tid * 4];
    float4 o;
    o.x = (x.x - mean) * inv * wv.x + bv.x;
    o.y = (x.y - mean) * inv * wv.y + bv.y;
    o.z = (x.z - mean) * inv * wv.z + bv.z;
    o.w = (x.w - mean) * inv * wv.w + bv.w;
    *(float4*)&out[(size_t)row * HIDDEN + tid * 4] = o;
}

// ---------------- GroupNorm (4 groups of 128) fused with SiLU gate product ----------------
__global__ void __launch_bounds__(128) gn_gate_kernel(const float* __restrict__ Yh,
                                                      const float* __restrict__ w,
                                                      const float* __restrict__ b,
                                                      const float* __restrict__ G,
                                                      float* __restrict__ P)
{
    int row  = blockIdx.x;
    int tid  = threadIdx.x;
    int wi   = tid >> 5;
    int lane = tid & 31;
    int d = wi * HD + lane * 4;
    float4 y = *(const float4*)&Yh[(size_t)row * HIDDEN + d];
    float s = y.x + y.y + y.z + y.w;
    float q = y.x*y.x + y.y*y.y + y.z*y.z + y.w*y.w;
    #pragma unroll
    for (int o = 16; o > 0; o >>= 1) {
        s += __shfl_xor_sync(0xffffffffu, s, o);
        q += __shfl_xor_sync(0xffffffffu, q, o);
    }
    float mean = s * (1.0f / HD);
    float var  = q * (1.0f / HD) - mean * mean;
    float inv  = rsqrtf(var + EPS);
    float4 wv = *(const float4*)&w[d];
    float4 bv = *(const float4*)&b[d];
    float4 gv = *(const float4*)&G[(size_t)row * HIDDEN + d];
    float4 o;
    o.x = ((y.x - mean) * inv * wv.x + bv.x) * gv.x;
    o.y = ((y.y - mean) * inv * wv.y + bv.y) * gv.y;
    o.z = ((y.z - mean) * inv * wv.z + bv.z) * gv.z;
    o.w = ((y.w - mean) * inv * wv.w + bv.w) * gv.w;
    *(float4*)&P[(size_t)row * HIDDEN + d] = o;
}

// ---------------- generic SGEMM 64x64x16, 256 threads, 4x4 frags ----------------
#define BM 64
#define BN 64
#define BK 16

constexpr int EPI_NONE = 0;
constexpr int EPI_SILU = 1;
constexpr int EPI_RES = 2;
constexpr int EPI_BIAS_GELU = 3;
constexpr int EPI_BIAS_RES = 4;

template<int EPI>
__global__ void __launch_bounds__(256) sgemm_kernel(
    const float* __restrict__ A, const float* __restrict__ Bmat,
    float* __restrict__ C, int M, int N, int K, int headed,
    const float* __restrict__ bias, const float* __restrict__ res)
{
    __shared__ float As[BM][BK];
    __shared__ float Bs[BK][BN];
    int tid = threadIdx.x;
    int tx = tid & 15, ty = tid >> 4;
    int m0 = blockIdx.y * BM;
    int n0 = blockIdx.x * BN;

    const float* Bptr;
    int ldb, ncol;
    if (headed) {   // B[k,n] = W[h, k, e]; tiles never cross head boundary (BN=64, head=128)
        int head = n0 >> 7;
        Bptr = Bmat + (size_t)head * K * HD;
        ldb = HD;
        ncol = n0 & 127;
    } else {
        Bptr = Bmat;
        ldb = N;
        ncol = n0;
    }

    float acc[4][4] = {};
    int arow = tid >> 2, acol = (tid & 3) * 4;     // 64x16 A tile
    int brow = tid >> 4, bcol = (tid & 15) * 4;    // 16x64 B tile

    for (int k0 = 0; k0 < K; k0 += BK) {
        float4 av = *(const float4*)&A[(size_t)(m0 + arow) * K + k0 + acol];
        *(float4*)&As[arow][acol] = av;
        float4 bv = *(const float4*)&Bptr[(size_t)(k0 + brow) * ldb + ncol + bcol];
        *(float4*)&Bs[brow][bcol] = bv;
        __syncthreads();
        #pragma unroll
        for (int k = 0; k < BK; k++) {
            float a[4];
            #pragma unroll
            for (int i = 0; i < 4; i++) a[i] = As[ty * 4 + i][k];
            float4 b4 = *(const float4*)&Bs[k][tx * 4];
            #pragma unroll
            for (int i = 0; i < 4; i++) {
                acc[i][0] += a[i] * b4.x;
                acc[i][1] += a[i] * b4.y;
                acc[i][2] += a[i] * b4.z;
                acc[i][3] += a[i] * b4.w;
            }
        }
        __syncthreads();
    }

    #pragma unroll
    for (int i = 0; i < 4; i++) {
        int row = m0 + ty * 4 + i;
        int col0 = n0 + tx * 4;
        float4 o;
        float v[4];
        #pragma unroll
        for (int j = 0; j < 4; j++) {
            float x = acc[i][j];
            int col = col0 + j;
            if (EPI == EPI_SILU) {
                x = x / (1.0f + expf(-x));
            } else if (EPI == EPI_RES) {
                x = x + res[(size_t)row * N + col];
            } else if (EPI == EPI_BIAS_GELU) {
                x = x + bias[col];
                x = 0.5f * x * (1.0f + erff(x * 0.70710678118654752f));
            } else if (EPI == EPI_BIAS_RES) {
                x = x + bias[col] + res[(size_t)row * N + col];
            }
            v[j] = x;
        }
        o.x = v[0]; o.y = v[1]; o.z = v[2]; o.w = v[3];
        *(float4*)&C[(size_t)row * N + col0] = o;
    }
}

// ---------------- fused causal retention: per (b,h), 64-row blocks ----------------
#define QS_LD 132
#define SS_LD 68
#define ATT_SMEM ((2*64*QS_LD + 64*SS_LD) * (int)sizeof(float))   // 84992 B

__global__ void __launch_bounds__(256) attn_kernel(
    const float* __restrict__ Q, const float* __restrict__ Kt,
    const float* __restrict__ V, float* __restrict__ Yh,
    const float* __restrict__ powtab)
{
    extern __shared__ float sm[];
    float* Qs  = sm;                     // [64][132]
    float* KVs = sm + 64 * QS_LD;        // [64][132] (K then reused for V)
    float* Ss  = sm + 2 * 64 * QS_LD;    // [64][68]

    int tid = threadIdx.x;
    int tx = tid & 15, ty = tid >> 4;
    int bh = blockIdx.y;
    int b = bh >> 2;
    int h = bh & 3;
    int row0 = blockIdx.x * 64;
    const float* pw = powtab + h * SSEQ;

    int lr = tid >> 5;          // 0..7
    int le = (tid & 31) * 4;    // 0..124

    // load Q tile [64][128]
    #pragma unroll
    for (int i = 0; i < 8; i++) {
        int rr = lr + i * 8;
        float4 v = *(const float4*)&Q[((size_t)(b * SSEQ + row0 + rr) * HIDDEN) + h * HD + le];
        *(float4*)&Qs[rr * QS_LD + le] = v;
    }

    float racc[4][8] = {};

    for (int tb = 0; tb <= blockIdx.x; tb++) {
        int t0 = tb * 64;
        __syncthreads();   // previous SV reads of KVs done (and first iter: nothing)
        #pragma unroll
        for (int i = 0; i < 8; i++) {
            int rr = lr + i * 8;
            float4 v = *(const float4*)&Kt[((size_t)(b * SSEQ + t0 + rr) * HIDDEN) + h * HD + le];
            *(float4*)&KVs[rr * QS_LD + le] = v;
        }
        __syncthreads();

        // S = Q K^T (64x64, reduce over 128)
        float sacc[4][4] = {};
        #pragma unroll
        for (int e4 = 0; e4 < HD; e4 += 4) {
            float4 qv[4], kv[4];
            #pragma unroll
            for (int i = 0; i < 4; i++) qv[i] = *(const float4*)&Qs[(ty * 4 + i) * QS_LD + e4];
            #pragma unroll
            for (int j = 0; j < 4; j++) kv[j] = *(const float4*)&KVs[(tx * 4 + j) * QS_LD + e4];
            #pragma unroll
            for (int i = 0; i < 4; i++)
                #pragma unroll
                for (int j = 0; j < 4; j++)
                    sacc[i][j] += qv[i].x * kv[j].x + qv[i].y * kv[j].y
                                + qv[i].z * kv[j].z + qv[i].w * kv[j].w;
        }

        // causal decay mask, stage to smem
        #pragma unroll
        for (int i = 0; i < 4; i++) {
            int gr = row0 + ty * 4 + i;
            #pragma unroll
            for (int j = 0; j < 4; j++) {
                int gc = t0 + tx * 4 + j;
                int d = gr - gc;
                float val = (d >= 0) ? sacc[i][j] * pw[d] : 0.0f;
                Ss[(ty * 4 + i) * SS_LD + tx * 4 + j] = val;
            }
        }
        __syncthreads();   // Ss visible, KVs reads done -> safe to overwrite with V

        #pragma unroll
        for (int i = 0; i < 8; i++) {
            int rr = lr + i * 8;
            float4 v = *(const float4*)&V[((size_t)(b * SSEQ + t0 + rr) * HIDDEN) + h * HD + le];
            *(float4*)&KVs[rr * QS_LD + le] = v;
        }
        __syncthreads();

        // ret += S @ V  (thread covers rows ty*4+i, cols tx*8+j)
        #pragma unroll 4
        for (int t = 0; t < 64; t++) {
            float sv[4];
            #pragma unroll
            for (int i = 0; i < 4; i++) sv[i] = Ss[(ty * 4 + i) * SS_LD + t];
            float4 va = *(const float4*)&KVs[t * QS_LD + tx * 8];
            float4 vb = *(const float4*)&KVs[t * QS_LD + tx * 8 + 4];
            #pragma unroll
            for (int i = 0; i < 4; i++) {
                racc[i][0] += sv[i] * va.x; racc[i][1] += sv[i] * va.y;
                racc[i][2] += sv[i] * va.z; racc[i][3] += sv[i] * va.w;
                racc[i][4] += sv[i] * vb.x; racc[i][5] += sv[i] * vb.y;
                racc[i][6] += sv[i] * vb.z; racc[i][7] += sv[i] * vb.w;
            }
        }
    }

    // write Yh[b, s, h*128 + c]
    #pragma unroll
    for (int i = 0; i < 4; i++) {
        int gr = row0 + ty * 4 + i;
        size_t base = (size_t)(b * SSEQ + gr) * HIDDEN + h * HD + tx * 8;
        float4 o1, o2;
        o1.x = racc[i][0]; o1.y = racc[i][1]; o1.z = racc[i][2]; o1.w = racc[i][3];
        o2.x = racc[i][4]; o2.y = racc[i][5]; o2.z = racc[i][6]; o2.w = racc[i][7];
        *(float4*)&Yh[base] = o1;
        *(float4*)&Yh[base + 4] = o2;
    }
}

// ---------------- host orchestration ----------------
struct DevPtrs {
    float *X, *Xn, *Q, *K, *V, *Yh, *G, *P, *Y, *Yn, *F, *pw, *cu, *su, *cd, *sd;
};

static void get_ptrs(DevPtrs& p)
{
    cudaGetSymbolAddress((void**)&p.X,  g_X);
    cudaGetSymbolAddress((void**)&p.Xn, g_Xn);
    cudaGetSymbolAddress((void**)&p.Q,  g_Q);
    cudaGetSymbolAddress((void**)&p.K,  g_K);
    cudaGetSymbolAddress((void**)&p.V,  g_V);
    cudaGetSymbolAddress((void**)&p.Yh, g_Yh);
    cudaGetSymbolAddress((void**)&p.G,  g_G);
    cudaGetSymbolAddress((void**)&p.P,  g_P);
    cudaGetSymbolAddress((void**)&p.Y,  g_Y);
    cudaGetSymbolAddress((void**)&p.Yn, g_Yn);
    cudaGetSymbolAddress((void**)&p.F,  g_F);
    cudaGetSymbolAddress((void**)&p.pw, g_pow);
    cudaGetSymbolAddress((void**)&p.cu, g_cu);
    cudaGetSymbolAddress((void**)&p.su, g_su);
    cudaGetSymbolAddress((void**)&p.cd, g_cd);
    cudaGetSymbolAddress((void**)&p.sd, g_sd);
}

extern "C" void kernel_launch(void* const* d_in, const int* in_sizes, int n_in,
                              void* d_out, int out_size)
{
    DevPtrs p;
    get_ptrs(p);
    cudaFuncSetAttribute(attn_kernel, cudaFuncAttributeMaxDynamicSharedMemorySize, ATT_SMEM);

    const float* X    = (const float*)d_in[0];
    const float* Wq   = (const float*)d_in[1];
    const float* Wk   = (const float*)d_in[2];
    const float* Wv   = (const float*)d_in[3];
    const float* Wg   = (const float*)d_in[4];
    const float* Wo   = (const float*)d_in[5];
    const float* gnw  = (const float*)d_in[6];
    const float* gnb  = (const float*)d_in[7];
    const float* ln1w = (const float*)d_in[8];
    const float* ln1b = (const float*)d_in[9];
    const float* ln2w = (const float*)d_in[10];
    const float* ln2b = (const float*)d_in[11];
    const float* f1w  = (const float*)d_in[12];
    const float* f1b  = (const float*)d_in[13];
    const float* f2w  = (const float*)d_in[14];
    const float* f2b  = (const float*)d_in[15];

    cudaMemcpyAsync(p.X, X, (size_t)NROWS * HIDDEN * sizeof(float),
                    cudaMemcpyDeviceToDevice, 0);
    xpos_tables_kernel<<<(SSEQ * HD + 255) / 256, 256>>>(p.cu, p.su, p.cd, p.sd);
    pow_kernel<<<(HEADS * SSEQ + 255) / 256, 256>>>(p.pw);

    dim3 g512(HIDDEN / BN, NROWS / BM);   // (8, 64)
    dim3 gFFN(FFND / BN, NROWS / BM);     // (16, 64)
    dim3 gatt(SSEQ / 64, BB * HEADS);     // (32, 8)
    int nPairBlocks = (NROWS * 256 + 255) / 256;

    for (int i = 0; i < LAYERS; i++) {
        // Xn = LN1(X)
        ln_kernel<<<NROWS, 128>>>(p.X, ln1w + i * HIDDEN, ln1b + i * HIDDEN, p.Xn);
        // Q,K,V projections (per-head weight layout)
        sgemm_kernel<EPI_NONE><<<g512, 256>>>(p.Xn, Wq + (size_t)i * HEADS * HIDDEN * HD,
                                              p.Q, NROWS, HIDDEN, HIDDEN, 1, nullptr, nullptr);
        sgemm_kernel<EPI_NONE><<<g512, 256>>>(p.Xn, Wk + (size_t)i * HEADS * HIDDEN * HD,
                                              p.K, NROWS, HIDDEN, HIDDEN, 1, nullptr, nullptr);
        sgemm_kernel<EPI_NONE><<<g512, 256>>>(p.Xn, Wv + (size_t)i * HEADS * HIDDEN * HD,
                                              p.V, NROWS, HIDDEN, HIDDEN, 1, nullptr, nullptr);
        // xPos rotary (Q upscale, K downscale)
        xpos_apply_kernel<<<nPairBlocks, 256>>>(p.Q, p.cu, p.su);
        xpos_apply_kernel<<<nPairBlocks, 256>>>(p.K, p.cd, p.sd);
        // gate G = silu(Xn @ Wg)
        sgemm_kernel<EPI_SILU><<<g512, 256>>>(p.Xn, Wg + (size_t)i * HIDDEN * HIDDEN,
                                              p.G, NROWS, HIDDEN, HIDDEN, 0, nullptr, nullptr);
        // retention
        attn_kernel<<<gatt, 256, ATT_SMEM>>>(p.Q, p.K, p.V, p.Yh, p.pw);
        // P = gn(Yh) * G
        gn_gate_kernel<<<NROWS, 128>>>(p.Yh, gnw + i * HIDDEN, gnb + i * HIDDEN, p.G, p.P);
        // Y = P @ Wo + X
        sgemm_kernel<EPI_RES><<<g512, 256>>>(p.P, Wo + (size_t)i * HIDDEN * HIDDEN,
                                             p.Y, NROWS, HIDDEN, HIDDEN, 0, nullptr, p.X);
        // Yn = LN2(Y)
        ln_kernel<<<NROWS, 128>>>(p.Y, ln2w + i * HIDDEN, ln2b + i * HIDDEN, p.Yn);
        // F = gelu(Yn @ f1 + b1)
        sgemm_kernel<EPI_BIAS_GELU><<<gFFN, 256>>>(p.Yn, f1w + (size_t)i * HIDDEN * FFND,
                                                   p.F, NROWS, FFND, HIDDEN, 0,
                                                   f1b + i * FFND, nullptr);
        // X = F @ f2 + b2 + Y
        float* outp = (i == LAYERS - 1) ? (float*)d_out : p.X;
        sgemm_kernel<EPI_BIAS_RES><<<g512, 256>>>(p.F, f2w + (size_t)i * FFND * HIDDEN,
                                                  outp, NROWS, HIDDEN, FFND, 0,
                                                  f2b + i * HIDDEN, p.Y);
    }
}

// round 3
// speedup vs baseline: 3.0938x; 3.0938x over previous
#include <cuda_runtime.h>
#include <cuda_bf16.h>
#include <math.h>
#include <stdint.h>

typedef __nv_bfloat16  bf16;
typedef __nv_bfloat162 bf162;

#define LAYERS 4
#define HIDDEN 512
#define FFND   1024
#define HEADS  4
#define BB     2
#define SSEQ   2048
#define HD     128
#define NROWS  (BB*SSEQ)
#define EPS    1e-5f

// ----------------- static device buffers -----------------
__device__ float gX  [NROWS*HIDDEN];
__device__ float gQKV[NROWS*1536];
__device__ float gG  [NROWS*HIDDEN];
__device__ float gYh [NROWS*HIDDEN];
__device__ float gY  [NROWS*HIDDEN];
__device__ bf16 gXnH[NROWS*HIDDEN], gXnL[NROWS*HIDDEN];
__device__ bf16 gQH [NROWS*HIDDEN], gQL [NROWS*HIDDEN];
__device__ bf16 gKH [NROWS*HIDDEN], gKL [NROWS*HIDDEN];
__device__ bf16 gVH [NROWS*HIDDEN], gVL [NROWS*HIDDEN];
__device__ bf16 gPH [NROWS*HIDDEN], gPL [NROWS*HIDDEN];
__device__ bf16 gYnH[NROWS*HIDDEN], gYnL[NROWS*HIDDEN];
__device__ bf16 gFH [NROWS*FFND],   gFL [NROWS*FFND];
__device__ bf16 gWqkvH[LAYERS*512*1536], gWqkvL[LAYERS*512*1536];
__device__ bf16 gWgH[LAYERS*512*512], gWgL[LAYERS*512*512];
__device__ bf16 gWoH[LAYERS*512*512], gWoL[LAYERS*512*512];
__device__ bf16 gF1H[LAYERS*512*1024], gF1L[LAYERS*512*1024];
__device__ bf16 gF2H[LAYERS*1024*512], gF2L[LAYERS*1024*512];
__device__ float gPow[HEADS*SSEQ];
__device__ float gCu[SSEQ*HD], gSu[SSEQ*HD], gCd[SSEQ*HD], gSd[SSEQ*HD];

// ----------------- helpers -----------------
__device__ __forceinline__ void cp16(uint32_t dst, const void* src) {
    asm volatile("cp.async.cg.shared.global [%0], [%1], 16;" :: "r"(dst), "l"(src));
}
__device__ __forceinline__ void cpc() { asm volatile("cp.async.commit_group;"); }
__device__ __forceinline__ void cpw0() { asm volatile("cp.async.wait_group 0;"); }
__device__ __forceinline__ void cpw1() { asm volatile("cp.async.wait_group 1;"); }
__device__ __forceinline__ void ldsm4(uint32_t* r, uint32_t a) {
    asm volatile("ldmatrix.sync.aligned.m8n8.x4.shared.b16 {%0,%1,%2,%3}, [%4];"
                 : "=r"(r[0]), "=r"(r[1]), "=r"(r[2]), "=r"(r[3]) : "r"(a));
}
__device__ __forceinline__ void ldsm2(uint32_t* r, uint32_t a) {
    asm volatile("ldmatrix.sync.aligned.m8n8.x2.shared.b16 {%0,%1}, [%2];"
                 : "=r"(r[0]), "=r"(r[1]) : "r"(a));
}
__device__ __forceinline__ void ldsm2t(uint32_t* r, uint32_t a) {
    asm volatile("ldmatrix.sync.aligned.m8n8.x2.trans.shared.b16 {%0,%1}, [%2];"
                 : "=r"(r[0]), "=r"(r[1]) : "r"(a));
}
__device__ __forceinline__ void mma16816(float* c, const uint32_t* a, const uint32_t* b) {
    asm volatile("mma.sync.aligned.m16n8k16.row.col.f32.bf16.bf16.f32 "
                 "{%0,%1,%2,%3},{%4,%5,%6,%7},{%8,%9},{%0,%1,%2,%3};"
                 : "+f"(c[0]), "+f"(c[1]), "+f"(c[2]), "+f"(c[3])
                 : "r"(a[0]), "r"(a[1]), "r"(a[2]), "r"(a[3]), "r"(b[0]), "r"(b[1]));
}
__device__ __forceinline__ void split2(float x, bf16& h, bf16& l) {
    h = __float2bfloat16_rn(x);
    l = __float2bfloat16_rn(x - __bfloat162float(h));
}
__device__ __forceinline__ uint32_t packhi(float a, float b) {
    bf162 t = __floats2bfloat162_rn(a, b); return *(uint32_t*)&t;
}
__device__ __forceinline__ uint32_t packlo(float a, float b) {
    float ah = __bfloat162float(__float2bfloat16_rn(a));
    float bh = __bfloat162float(__float2bfloat16_rn(b));
    bf162 t = __floats2bfloat162_rn(a - ah, b - bh); return *(uint32_t*)&t;
}

// ----------------- tables -----------------
__global__ void xpos_tables_kernel(float* cu, float* su, float* cd, float* sd)
{
    int idx = blockIdx.x * blockDim.x + threadIdx.x;
    if (idx >= SSEQ * HD) return;
    int pos = idx / HD;
    int j   = (idx % HD) >> 1;
    float sj = (2.0f * j + 0.4f * HD) / (1.4f * HD);
    double scale = pow((double)sj, (double)pos / 512.0);
    float invf = (float)(1.0 / pow(10000.0, (double)j / 64.0));
    float angf = (float)pos * invf;
    double ang = (double)angf;
    float sn = (float)sin(ang), cs = (float)cos(ang);
    float sc = (float)scale, isc = (float)(1.0 / scale);
    cu[idx] = cs * sc;  su[idx] = sn * sc;
    cd[idx] = cs * isc; sd[idx] = sn * isc;
}
__global__ void pow_kernel(float* powtab)
{
    int idx = blockIdx.x * blockDim.x + threadIdx.x;
    if (idx >= HEADS * SSEQ) return;
    int h = idx / SSEQ, d = idx % SSEQ;
    double lg = log(1.0/32.0) + (double)h * (log(1.0/512.0) - log(1.0/32.0)) / (HEADS - 1);
    double gamma = 1.0 - exp(lg);
    powtab[idx] = (float)exp((double)d * log(gamma));
}

// ----------------- weight packing -----------------
__global__ void pack_qkv_kernel(const float* __restrict__ Wq, const float* __restrict__ Wk,
                                const float* __restrict__ Wv,
                                bf16* __restrict__ Bh, bf16* __restrict__ Bl)
{
    size_t idx = (size_t)blockIdx.x * 256 + threadIdx.x;
    if (idx >= (size_t)LAYERS * 512 * 1536) return;
    int n = idx % 1536;
    int k = (idx / 1536) % 512;
    int l = idx / (1536 * 512);
    int sel = n / 512, h = (n % 512) / 128, e = n % 128;
    const float* W = (sel == 0) ? Wq : (sel == 1) ? Wk : Wv;
    split2(W[(((size_t)l * HEADS + h) * 512 + k) * 128 + e], Bh[idx], Bl[idx]);
}
__global__ void pack_mat_kernel(const float* __restrict__ W,
                                bf16* __restrict__ Bh, bf16* __restrict__ Bl, int total)
{
    int idx = blockIdx.x * 256 + threadIdx.x;
    if (idx < total) split2(W[idx], Bh[idx], Bl[idx]);
}

// ----------------- LayerNorm -> split -----------------
__global__ void __launch_bounds__(128) ln_split_kernel(const float* __restrict__ X,
    const float* __restrict__ w, const float* __restrict__ b,
    bf16* __restrict__ oh, bf16* __restrict__ ol)
{
    int row = blockIdx.x, tid = threadIdx.x;
    float4 x = *(const float4*)&X[(size_t)row * HIDDEN + tid * 4];
    float s = x.x + x.y + x.z + x.w;
    float q = x.x*x.x + x.y*x.y + x.z*x.z + x.w*x.w;
    #pragma unroll
    for (int o = 16; o > 0; o >>= 1) {
        s += __shfl_xor_sync(~0u, s, o); q += __shfl_xor_sync(~0u, q, o);
    }
    __shared__ float ss[4], qq[4];
    if ((tid & 31) == 0) { ss[tid >> 5] = s; qq[tid >> 5] = q; }
    __syncthreads();
    float S = ss[0]+ss[1]+ss[2]+ss[3], Qs = qq[0]+qq[1]+qq[2]+qq[3];
    float mean = S * (1.0f / HIDDEN);
    float var  = Qs * (1.0f / HIDDEN) - mean * mean;
    float inv  = rsqrtf(var + EPS);
    float4 wv = *(const float4*)&w[tid*4];
    float4 bv = *(const float4*)&b[tid*4];
    float v0 = (x.x-mean)*inv*wv.x + bv.x, v1 = (x.y-mean)*inv*wv.y + bv.y;
    float v2 = (x.z-mean)*inv*wv.z + bv.z, v3 = (x.w-mean)*inv*wv.w + bv.w;
    size_t o0 = (size_t)row * HIDDEN + tid * 4;
    bf16 h0,l0,h1,l1,h2,l2,h3,l3;
    split2(v0,h0,l0); split2(v1,h1,l1); split2(v2,h2,l2); split2(v3,h3,l3);
    *(bf162*)&oh[o0] = bf162(h0,h1); *(bf162*)&oh[o0+2] = bf162(h2,h3);
    *(bf162*)&ol[o0] = bf162(l0,l1); *(bf162*)&ol[o0+2] = bf162(l2,l3);
}

// ----------------- GroupNorm * gate -> split -----------------
__global__ void __launch_bounds__(128) gn_gate_split_kernel(const float* __restrict__ Yh,
    const float* __restrict__ w, const float* __restrict__ b,
    const float* __restrict__ G, bf16* __restrict__ oh, bf16* __restrict__ ol)
{
    int row = blockIdx.x, tid = threadIdx.x;
    int d = (tid >> 5) * HD + (tid & 31) * 4;
    float4 y = *(const float4*)&Yh[(size_t)row * HIDDEN + d];
    float s = y.x + y.y + y.z + y.w;
    float q = y.x*y.x + y.y*y.y + y.z*y.z + y.w*y.w;
    #pragma unroll
    for (int o = 16; o > 0; o >>= 1) {
        s += __shfl_xor_sync(~0u, s, o); q += __shfl_xor_sync(~0u, q, o);
    }
    float mean = s * (1.0f / HD);
    float var  = q * (1.0f / HD) - mean * mean;
    float inv  = rsqrtf(var + EPS);
    float4 wv = *(const float4*)&w[d];
    float4 bv = *(const float4*)&b[d];
    float4 gv = *(const float4*)&G[(size_t)row * HIDDEN + d];
    float v0 = ((y.x-mean)*inv*wv.x + bv.x)*gv.x, v1 = ((y.y-mean)*inv*wv.y + bv.y)*gv.y;
    float v2 = ((y.z-mean)*inv*wv.z + bv.z)*gv.z, v3 = ((y.w-mean)*inv*wv.w + bv.w)*gv.w;
    size_t o0 = (size_t)row * HIDDEN + d;
    bf16 h0,l0,h1,l1,h2,l2,h3,l3;
    split2(v0,h0,l0); split2(v1,h1,l1); split2(v2,h2,l2); split2(v3,h3,l3);
    *(bf162*)&oh[o0] = bf162(h0,h1); *(bf162*)&oh[o0+2] = bf162(h2,h3);
    *(bf162*)&ol[o0] = bf162(l0,l1); *(bf162*)&ol[o0+2] = bf162(l2,l3);
}

// ----------------- xPos + split (from fused QKV f32) -----------------
__global__ void xpos_split_kernel(const float* __restrict__ QKV, int coloff,
    const float* __restrict__ ct, const float* __restrict__ st,
    bf16* __restrict__ oh, bf16* __restrict__ ol)
{
    int idx = blockIdx.x * 256 + threadIdx.x;
    if (idx >= NROWS * 256) return;
    int r = idx >> 8, pe = idx & 255;
    int h = pe >> 6, j = pe & 63;
    int pos = r & (SSEQ - 1);
    size_t src = (size_t)r * 1536 + coloff + h * HD + 2 * j;
    float x1 = QKV[src], x2 = QKV[src + 1];
    int ti = pos * HD + 2 * j;
    float c = ct[ti], s = st[ti];
    float y1 = x1 * c - x2 * s;
    float y2 = x2 * c + x1 * s;
    bf16 h1,l1,h2,l2;
    split2(y1,h1,l1); split2(y2,h2,l2);
    size_t dst = (size_t)r * HIDDEN + h * HD + 2 * j;
    *(bf162*)&oh[dst] = bf162(h1,h2);
    *(bf162*)&ol[dst] = bf162(l1,l2);
}
__global__ void vsplit_kernel(const float* __restrict__ QKV,
                              bf16* __restrict__ oh, bf16* __restrict__ ol)
{
    int idx = blockIdx.x * 256 + threadIdx.x;
    if (idx >= NROWS * 256) return;
    int r = idx >> 8, c = (idx & 255) * 2;
    size_t src = (size_t)r * 1536 + 1024 + c;
    float v0 = QKV[src], v1 = QKV[src + 1];
    bf16 h0,l0,h1,l1;
    split2(v0,h0,l0); split2(v1,h1,l1);
    size_t dst = (size_t)r * HIDDEN + c;
    *(bf162*)&oh[dst] = bf162(h0,h1);
    *(bf162*)&ol[dst] = bf162(l0,l1);
}

// ----------------- split-bf16 MMA GEMM 128x64x32 -----------------
#define GBM 128
#define GBN 64
#define GBK 32
#define ALD 40
#define BLD 72

constexpr int EPI_F32 = 0, EPI_SILU = 1, EPI_RES = 2, EPI_GELUS = 3, EPI_BRES = 4;

template<int EPI>
__global__ void __launch_bounds__(256) mma_gemm(
    const bf16* __restrict__ Ah, const bf16* __restrict__ Al,
    const bf16* __restrict__ Bh, const bf16* __restrict__ Bl,
    float* __restrict__ C, bf16* __restrict__ Ch, bf16* __restrict__ Cl,
    int M, int N, int K,
    const float* __restrict__ bias, const float* __restrict__ res)
{
    __shared__ __align__(16) bf16 As[2][GBM * ALD];
    __shared__ __align__(16) bf16 Bs[2][GBK * BLD];
    int tid = threadIdx.x, lane = tid & 31, wid = tid >> 5;
    int wm = wid >> 1, wn = wid & 1;
    int bm0 = blockIdx.y * GBM, bn0 = blockIdx.x * GBN;
    uint32_t asb = (uint32_t)__cvta_generic_to_shared(&As[0][0]);
    uint32_t bsb = (uint32_t)__cvta_generic_to_shared(&Bs[0][0]);
    const bf16* Aseg[3] = {Ah, Ah, Al};
    const bf16* Bseg[3] = {Bh, Bl, Bh};
    int kcps = K / GBK, total = 3 * kcps;
    int a_row0 = tid >> 2, a_off = (tid & 3) * 8;
    int b_row = tid >> 3,  b_off = (tid & 7) * 8;

    auto load = [&](int c, int bf) {
        int seg = c / kcps;
        int k0 = (c - seg * kcps) * GBK;
        const bf16* Ag = Aseg[seg];
        const bf16* Bg = Bseg[seg];
        cp16(asb + (uint32_t)(bf * GBM * ALD + a_row0 * ALD + a_off) * 2,
             Ag + (size_t)(bm0 + a_row0) * K + k0 + a_off);
        cp16(asb + (uint32_t)(bf * GBM * ALD + (a_row0 + 64) * ALD + a_off) * 2,
             Ag + (size_t)(bm0 + a_row0 + 64) * K + k0 + a_off);
        cp16(bsb + (uint32_t)(bf * GBK * BLD + b_row * BLD + b_off) * 2,
             Bg + (size_t)(k0 + b_row) * N + bn0 + b_off);
        cpc();
    };

    float acc[2][4][4] = {};
    int l15 = lane & 15, l16 = (lane >> 4) * 8;
    int l7 = lane & 7,  l8 = ((lane & 15) >> 3) * 8;

    load(0, 0);
    for (int c = 0; c < total; c++) {
        int buf = c & 1;
        if (c + 1 < total) { load(c + 1, buf ^ 1); cpw1(); }
        else cpw0();
        __syncthreads();
        uint32_t ap = asb + (uint32_t)(buf * GBM * ALD) * 2;
        uint32_t bp = bsb + (uint32_t)(buf * GBK * BLD) * 2;
        #pragma unroll
        for (int kk = 0; kk < 2; kk++) {
            uint32_t a[2][4];
            #pragma unroll
            for (int mt = 0; mt < 2; mt++)
                ldsm4(a[mt], ap + (uint32_t)((wm*32 + mt*16 + l15) * ALD + kk*16 + l16) * 2);
            uint32_t bfrag[4][2];
            #pragma unroll
            for (int nt = 0; nt < 4; nt++)
                ldsm2t(bfrag[nt], bp + (uint32_t)((kk*16 + l15) * BLD + wn*32 + nt*8) * 2);
            #pragma unroll
            for (int mt = 0; mt < 2; mt++)
                #pragma unroll
                for (int nt = 0; nt < 4; nt++)
                    mma16816(acc[mt][nt], a[mt], bfrag[nt]);
        }
        __syncthreads();
    }
    (void)l7; (void)l8;

    int rbase = bm0 + wm * 32 + (lane >> 2);
    int cbase = bn0 + wn * 32 + (lane & 3) * 2;
    #pragma unroll
    for (int mt = 0; mt < 2; mt++)
        #pragma unroll
        for (int nt = 0; nt < 4; nt++)
            #pragma unroll
            for (int half = 0; half < 2; half++) {
                int r = rbase + mt * 16 + half * 8;
                int cc = cbase + nt * 8;
                float x0 = acc[mt][nt][half*2], x1 = acc[mt][nt][half*2+1];
                if (EPI == EPI_SILU) {
                    x0 = x0 / (1.0f + expf(-x0)); x1 = x1 / (1.0f + expf(-x1));
                } else if (EPI == EPI_RES) {
                    x0 += res[(size_t)r*N+cc]; x1 += res[(size_t)r*N+cc+1];
                } else if (EPI == EPI_GELUS) {
                    x0 += bias[cc]; x1 += bias[cc+1];
                    x0 = 0.5f*x0*(1.0f + erff(x0*0.70710678118654752f));
                    x1 = 0.5f*x1*(1.0f + erff(x1*0.70710678118654752f));
                } else if (EPI == EPI_BRES) {
                    x0 += bias[cc] + res[(size_t)r*N+cc];
                    x1 += bias[cc+1] + res[(size_t)r*N+cc+1];
                }
                if (EPI == EPI_GELUS) {
                    bf16 h0,l0,h1,l1;
                    split2(x0,h0,l0); split2(x1,h1,l1);
                    *(bf162*)&Ch[(size_t)r*N+cc] = bf162(h0,h1);
                    *(bf162*)&Cl[(size_t)r*N+cc] = bf162(l0,l1);
                } else {
                    float2 o; o.x = x0; o.y = x1;
                    *(float2*)&C[(size_t)r*N+cc] = o;
                }
            }
}

// ----------------- fused retention (tensor cores) -----------------
#define ALD2 136
#define PLB  (64 * ALD2 * 2)                 // bytes/plane = 17408
#define ATT_SMEM (10 * PLB + SSEQ * 4)       // 182272

__global__ void __launch_bounds__(256, 1) attn_mma(
    const bf16* __restrict__ Qh, const bf16* __restrict__ Ql,
    const bf16* __restrict__ Kh, const bf16* __restrict__ Kl,
    const bf16* __restrict__ Vh, const bf16* __restrict__ Vl,
    float* __restrict__ Yout, const float* __restrict__ powtab)
{
    extern __shared__ __align__(16) unsigned char smraw[];
    uint32_t sb = (uint32_t)__cvta_generic_to_shared(smraw);
    float* pws = (float*)(smraw + 10 * PLB);
    float* red = (float*)smraw;   // overlaps Q planes (used after compute)

    int tid = threadIdx.x, lane = tid & 31, wid = tid >> 5;
    int wm = wid >> 1, wt = wid & 1;
    int bh = blockIdx.y, b = bh >> 2, h = bh & 3;
    int l15 = lane & 15, l16 = (lane >> 4) * 8;
    int l7 = lane & 7,  l8 = ((lane & 15) >> 3) * 8;

    for (int i = tid; i < SSEQ; i += 256) pws[i] = powtab[h * SSEQ + i];

    auto ldkv = [&](int t0, int buf) {
        uint32_t kb = sb + (2 + 2 * buf) * PLB;
        uint32_t vb = sb + (6 + 2 * buf) * PLB;
        #pragma unroll
        for (int i = 0; i < 4; i++) {
            int ch = tid + i * 256;
            int row = ch >> 4, off = (ch & 15) * 8;
            size_t g = (size_t)(b * SSEQ + t0 + row) * HIDDEN + h * HD + off;
            uint32_t d = (uint32_t)(row * ALD2 + off) * 2;
            cp16(kb + d, Kh + g);
            cp16(kb + PLB + d, Kl + g);
            cp16(vb + d, Vh + g);
            cp16(vb + PLB + d, Vl + g);
        }
    };

    for (int ph = 0; ph < 2; ph++) {
        int rb = (ph == 0) ? (int)blockIdx.x : 31 - (int)blockIdx.x;
        int row0 = rb * 64;
        __syncthreads();   // red/pws readers done before overwriting qs

        // Q tile + KV(tb=0) as group 0
        #pragma unroll
        for (int i = 0; i < 4; i++) {
            int ch = tid + i * 256;
            int row = ch >> 4, off = (ch & 15) * 8;
            size_t g = (size_t)(b * SSEQ + row0 + row) * HIDDEN + h * HD + off;
            uint32_t d = (uint32_t)(row * ALD2 + off) * 2;
            cp16(sb + d, Qh + g);
            cp16(sb + PLB + d, Ql + g);
        }
        ldkv(0, 0);
        cpc();

        float racc[16][4] = {};

        for (int tb = 0; tb <= rb; tb++) {
            int buf = tb & 1;
            if (tb + 1 <= rb) { ldkv((tb + 1) * 64, buf ^ 1); cpc(); cpw1(); }
            else cpw0();
            __syncthreads();

            uint32_t ku = sb + (2 + 2 * buf) * PLB;
            uint32_t vu = sb + (6 + 2 * buf) * PLB;

            // S = Q K^T  (warp strip: rows wm*16..+16, cols wt*32..+32)
            float sc[4][4] = {};
            #pragma unroll
            for (int kk = 0; kk < 8; kk++) {
                uint32_t qh[4], ql[4];
                uint32_t qa = sb + (uint32_t)((wm*16 + l15) * ALD2 + kk*16 + l16) * 2;
                ldsm4(qh, qa);
                ldsm4(ql, qa + PLB);
                #pragma unroll
                for (int nt = 0; nt < 4; nt++) {
                    int trow = wt * 32 + nt * 8 + l7;
                    uint32_t ka = ku + (uint32_t)(trow * ALD2 + kk*16 + l8) * 2;
                    uint32_t kbh[2], kbl[2];
                    ldsm2(kbh, ka);
                    ldsm2(kbl, ka + PLB);
                    mma16816(sc[nt], qh, kbh);
                    mma16816(sc[nt], qh, kbl);
                    mma16816(sc[nt], ql, kbh);
                }
            }

            // causal decay mask
            int t0 = tb * 64;
            int gr0 = row0 + wm * 16 + (lane >> 2);
            #pragma unroll
            for (int nt = 0; nt < 4; nt++) {
                int gc0 = t0 + wt * 32 + nt * 8 + (lane & 3) * 2;
                #pragma unroll
                for (int q = 0; q < 4; q++) {
                    int d = (gr0 + (q >> 1) * 8) - (gc0 + (q & 1));
                    sc[nt][q] = (d >= 0) ? sc[nt][q] * pws[d] : 0.0f;
                }
            }

            // ret += S V  (k = warp's 32 t-cols, two k16 chunks)
            #pragma unroll
            for (int kk2 = 0; kk2 < 2; kk2++) {
                int j0 = 2 * kk2, j1 = j0 + 1;
                uint32_t ah[4], al[4];
                ah[0] = packhi(sc[j0][0], sc[j0][1]); al[0] = packlo(sc[j0][0], sc[j0][1]);
                ah[1] = packhi(sc[j0][2], sc[j0][3]); al[1] = packlo(sc[j0][2], sc[j0][3]);
                ah[2] = packhi(sc[j1][0], sc[j1][1]); al[2] = packlo(sc[j1][0], sc[j1][1]);
                ah[3] = packhi(sc[j1][2], sc[j1][3]); al[3] = packlo(sc[j1][2], sc[j1][3]);
                int vrow = wt * 32 + kk2 * 16 + l15;
                #pragma unroll
                for (int nt = 0; nt < 16; nt++) {
                    uint32_t va = vu + (uint32_t)(vrow * ALD2 + nt * 8) * 2;
                    uint32_t vbh[2], vbl[2];
                    ldsm2t(vbh, va);
                    ldsm2t(vbl, va + PLB);
                    mma16816(racc[nt], ah, vbh);
                    mma16816(racc[nt], ah, vbl);
                    mma16816(racc[nt], al, vbh);
                }
            }
            __syncthreads();   // all reads of buf^1 done before next prefetch
        }

        // cross-warp (wt) reduction + writeout
        int rr = lane >> 2, cp2 = (lane & 3) * 2;
        if (wt == 1) {
            #pragma unroll
            for (int nt = 0; nt < 16; nt++) {
                int c = nt * 8 + cp2;
                *(float2*)&red[(wm*16 + rr) * 128 + c]     = make_float2(racc[nt][0], racc[nt][1]);
                *(float2*)&red[(wm*16 + rr + 8) * 128 + c] = make_float2(racc[nt][2], racc[nt][3]);
            }
        }
        __syncthreads();
        if (wt == 0) {
            #pragma unroll
            for (int nt = 0; nt < 16; nt++) {
                int c = nt * 8 + cp2;
                float2 p0 = *(float2*)&red[(wm*16 + rr) * 128 + c];
                float2 p1 = *(float2*)&red[(wm*16 + rr + 8) * 128 + c];
                size_t o0 = (size_t)(b*SSEQ + row0 + wm*16 + rr) * HIDDEN + h*HD + c;
                *(float2*)&Yout[o0] = make_float2(racc[nt][0] + p0.x, racc[nt][1] + p0.y);
                *(float2*)&Yout[o0 + 8*HIDDEN] = make_float2(racc[nt][2] + p1.x, racc[nt][3] + p1.y);
            }
        }
    }
}

// ----------------- host -----------------
#define GSYM(p, s) cudaGetSymbolAddress((void**)&p, s)

extern "C" void kernel_launch(void* const* d_in, const int* in_sizes, int n_in,
                              void* d_out, int out_size)
{
    (void)in_sizes; (void)n_in; (void)out_size;
    float *pX, *pQKV, *pG, *pYh, *pY, *pPow, *pCu, *pSu, *pCd, *pSd;
    bf16 *pXnH,*pXnL,*pQH,*pQL,*pKH,*pKL,*pVH,*pVL,*pPH,*pPL,*pYnH,*pYnL,*pFH,*pFL;
    bf16 *pWqH,*pWqL,*pWgH,*pWgL,*pWoH,*pWoL,*pF1H,*pF1L,*pF2H,*pF2L;
    GSYM(pX,gX); GSYM(pQKV,gQKV); GSYM(pG,gG); GSYM(pYh,gYh); GSYM(pY,gY);
    GSYM(pPow,gPow); GSYM(pCu,gCu); GSYM(pSu,gSu); GSYM(pCd,gCd); GSYM(pSd,gSd);
    GSYM(pXnH,gXnH); GSYM(pXnL,gXnL); GSYM(pQH,gQH); GSYM(pQL,gQL);
    GSYM(pKH,gKH); GSYM(pKL,gKL); GSYM(pVH,gVH); GSYM(pVL,gVL);
    GSYM(pPH,gPH); GSYM(pPL,gPL); GSYM(pYnH,gYnH); GSYM(pYnL,gYnL);
    GSYM(pFH,gFH); GSYM(pFL,gFL);
    GSYM(pWqH,gWqkvH); GSYM(pWqL,gWqkvL); GSYM(pWgH,gWgH); GSYM(pWgL,gWgL);
    GSYM(pWoH,gWoH); GSYM(pWoL,gWoL); GSYM(pF1H,gF1H); GSYM(pF1L,gF1L);
    GSYM(pF2H,gF2H); GSYM(pF2L,gF2L);

    cudaFuncSetAttribute(attn_mma, cudaFuncAttributeMaxDynamicSharedMemorySize, ATT_SMEM);

    const float* X    = (const float*)d_in[0];
    const float* Wq   = (const float*)d_in[1];
    const float* Wk   = (const float*)d_in[2];
    const float* Wv   = (const float*)d_in[3];
    const float* Wg   = (const float*)d_in[4];
    const float* Wo   = (const float*)d_in[5];
    const float* gnw  = (const float*)d_in[6];
    const float* gnb  = (const float*)d_in[7];
    const float* ln1w = (const float*)d_in[8];
    const float* ln1b = (const float*)d_in[9];
    const float* ln2w = (const float*)d_in[10];
    const float* ln2b = (const float*)d_in[11];
    const float* f1w  = (const float*)d_in[12];
    const float* f1b  = (const float*)d_in[13];
    const float* f2w  = (const float*)d_in[14];
    const float* f2b  = (const float*)d_in[15];

    cudaMemcpyAsync(pX, X, (size_t)NROWS*HIDDEN*4, cudaMemcpyDeviceToDevice, 0);
    xpos_tables_kernel<<<(SSEQ*HD+255)/256, 256>>>(pCu, pSu, pCd, pSd);
    pow_kernel<<<(HEADS*SSEQ+255)/256, 256>>>(pPow);
    pack_qkv_kernel<<<LAYERS*512*1536/256, 256>>>(Wq, Wk, Wv, pWqH, pWqL);
    pack_mat_kernel<<<LAYERS*512*512/256, 256>>>(Wg, pWgH, pWgL, LAYERS*512*512);
    pack_mat_kernel<<<LAYERS*512*512/256, 256>>>(Wo, pWoH, pWoL, LAYERS*512*512);
    pack_mat_kernel<<<LAYERS*512*1024/256, 256>>>(f1w, pF1H, pF1L, LAYERS*512*1024);
    pack_mat_kernel<<<LAYERS*1024*512/256, 256>>>(f2w, pF2H, pF2L, LAYERS*1024*512);

    dim3 gQKVg(1536/GBN, NROWS/GBM);  // (24,32)
    dim3 g512(512/GBN, NROWS/GBM);    // (8,32)
    dim3 gFFN(1024/GBN, NROWS/GBM);   // (16,32)
    dim3 gatt(16, BB*HEADS);

    for (int i = 0; i < LAYERS; i++) {
        ln_split_kernel<<<NROWS, 128>>>(pX, ln1w + i*HIDDEN, ln1b + i*HIDDEN, pXnH, pXnL);
        mma_gemm<EPI_F32><<<gQKVg, 256>>>(pXnH, pXnL,
            pWqH + (size_t)i*512*1536, pWqL + (size_t)i*512*1536,
            pQKV, nullptr, nullptr, NROWS, 1536, 512, nullptr, nullptr);
        xpos_split_kernel<<<NROWS, 256>>>(pQKV, 0,   pCu, pSu, pQH, pQL);
        xpos_split_kernel<<<NROWS, 256>>>(pQKV, 512, pCd, pSd, pKH, pKL);
        vsplit_kernel<<<NROWS, 256>>>(pQKV, pVH, pVL);
        mma_gemm<EPI_SILU><<<g512, 256>>>(pXnH, pXnL,
            pWgH + (size_t)i*512*512, pWgL + (size_t)i*512*512,
            pG, nullptr, nullptr, NROWS, 512, 512, nullptr, nullptr);
        attn_mma<<<gatt, 256, ATT_SMEM>>>(pQH, pQL, pKH, pKL, pVH, pVL, pYh, pPow);
        gn_gate_split_kernel<<<NROWS, 128>>>(pYh, gnw + i*HIDDEN, gnb + i*HIDDEN, pG, pPH, pPL);
        mma_gemm<EPI_RES><<<g512, 256>>>(pPH, pPL,
            pWoH + (size_t)i*512*512, pWoL + (size_t)i*512*512,
            pY, nullptr, nullptr, NROWS, 512, 512, nullptr, pX);
        ln_split_kernel<<<NROWS, 128>>>(pY, ln2w + i*HIDDEN, ln2b + i*HIDDEN, pYnH, pYnL);
        mma_gemm<EPI_GELUS><<<gFFN, 256>>>(pYnH, pYnL,
            pF1H + (size_t)i*512*1024, pF1L + (size_t)i*512*1024,
            nullptr, pFH, pFL, NROWS, 1024, 512, f1b + i*FFND, nullptr);
        float* outp = (i == LAYERS - 1) ? (float*)d_out : pX;
        mma_gemm<EPI_BRES><<<g512, 256>>>(pFH, pFL,
            pF2H + (size_t)i*1024*512, pF2L + (size_t)i*1024*512,
            outp, nullptr, nullptr, NROWS, 512, 1024, f2b + i*HIDDEN, pY);
    }
}